// round 14
// baseline (speedup 1.0000x reference)
#include <cuda_runtime.h>
#include <cuda_fp16.h>
#include <mma.h>
#include <cstdint>

using namespace nvcuda;

// ---------------- problem constants ----------------
#define Bc 4
#define Lc 4096
#define DMc 2048
#define Hc 32
#define Nc 128
#define Mrows (Bc * Lc)            // 16384
#define MH (Mrows / 2)             // 8192 (ladder half)
#define LDP (2 * Nc + Hc)          // 288
#define SEG 8
#define LSEG (Lc / SEG)            // 512
#define CHk 32

// ---------------- scratch (device globals; allocation-free) ----------------
__device__ __half g_xh [(size_t)Mrows * DMc];
__device__ __half g_Wxh[(size_t)DMc * LDP];
__device__ __half g_Wgh[(size_t)DMc * DMc];
__device__ __half g_Woh[(size_t)DMc * DMc];
__device__ float  g_P  [(size_t)Mrows * LDP];
__device__ float  g_Y  [(size_t)Mrows * Hc];
__device__ __half g_yf [(size_t)Mrows * DMc];
__device__ float  g_segstate[Bc * Hc * SEG * Nc];
__device__ float  g_segdecay[Bc * Hc * SEG * Nc];
__device__ float  g_seghin  [Bc * Hc * SEG * Nc];

// ---------------- side stream + events (host objects, created once) --------
struct StreamCtx {
    cudaStream_t s1;
    cudaEvent_t eglo, eout1;
    StreamCtx() {
        cudaStreamCreateWithFlags(&s1, cudaStreamNonBlocking);
        cudaEventCreateWithFlags(&eglo,  cudaEventDisableTiming);
        cudaEventCreateWithFlags(&eout1, cudaEventDisableTiming);
    }
};
static StreamCtx g_ctx;

// ---------------- cp.async helpers ----------------
__device__ __forceinline__ void cp16(void* smem, const void* gmem, int sz) {
    unsigned s = (unsigned)__cvta_generic_to_shared(smem);
    asm volatile("cp.async.cg.shared.global [%0], [%1], 16, %2;\n"
                 :: "r"(s), "l"(gmem), "r"(sz));
}
__device__ __forceinline__ void cp_commit() {
    asm volatile("cp.async.commit_group;\n");
}
template <int NWAIT>
__device__ __forceinline__ void cp_wait() {
    asm volatile("cp.async.wait_group %0;\n" :: "n"(NWAIT));
}

// ---------------- fused convert: x, Wx, Wg, Wo -> fp16 ----------------
#define C0 (Mrows * DMc / 4)               // x      8388608
#define C1 (C0 + DMc * LDP / 4)            // +Wx     147456
#define C2 (C1 + DMc * DMc / 4)            // +Wg    1048576
#define C3 (C2 + DMc * DMc / 4)            // +Wo    1048576

__device__ __forceinline__ void conv_one(
    int i, const float* __restrict__ x,  const float* __restrict__ Wx,
    const float* __restrict__ Wg, const float* __restrict__ Wo,
    __half* __restrict__ xh,  __half* __restrict__ Wxh,
    __half* __restrict__ Wgh, __half* __restrict__ Woh) {
    const float* src; __half* dst; int off;
    if (i < C0)      { src = x;  dst = xh;  off = i; }
    else if (i < C1) { src = Wx; dst = Wxh; off = i - C0; }
    else if (i < C2) { src = Wg; dst = Wgh; off = i - C1; }
    else             { src = Wo; dst = Woh; off = i - C2; }
    float4 v = reinterpret_cast<const float4*>(src)[off];
    __half2 a = __floats2half2_rn(v.x, v.y);
    __half2 b = __floats2half2_rn(v.z, v.w);
    uint2 r;
    r.x = *reinterpret_cast<uint32_t*>(&a);
    r.y = *reinterpret_cast<uint32_t*>(&b);
    reinterpret_cast<uint2*>(dst)[off] = r;
}

__global__ void __launch_bounds__(512)
conv_all(const float* __restrict__ x,  const float* __restrict__ Wx,
         const float* __restrict__ Wg, const float* __restrict__ Wo,
         __half* __restrict__ xh,  __half* __restrict__ Wxh,
         __half* __restrict__ Wgh, __half* __restrict__ Woh) {
    int base = blockIdx.x * 1024 + threadIdx.x;
    if (base < C3)       conv_one(base,       x, Wx, Wg, Wo, xh, Wxh, Wgh, Woh);
    if (base + 512 < C3) conv_one(base + 512, x, Wx, Wg, Wo, xh, Wxh, Wgh, Woh);
}

// ---------------- wmma GEMM: 128x128 tile, 4 warps, 64x64 warp tile --------
// EPI 0: direct fp32 store (N % 128 == 0)          (out = yf @ Wo)
// EPI 1: staged fp32 store with N edge             (P = x @ Wx)
// EPI 2: fused gate+yfull:
//        yf = (Y + x*Dp) * sigmoid(acc + bias), half2 stores
#define BM 128
#define BN 128
#define BKg 64
#define SKA 72
#define SKB 136
#define A_STG_H (BM * SKA)
#define B_STG_H (BKg * SKB)
#define A_BYTES (3 * A_STG_H * 2)
#define GEMM_DSMEM (A_BYTES + 3 * B_STG_H * 2)   // 107520
#define GT 128                                   // threads per GEMM CTA

template <int EPI>
__global__ void __launch_bounds__(GT)
gemm128(const __half* __restrict__ Ag, const __half* __restrict__ Bg,
        float* __restrict__ Cf, __half* __restrict__ Ch,
        const float* __restrict__ bias,
        const float* __restrict__ Y, const float* __restrict__ Dp,
        const __half* __restrict__ xh, int N, int K) {
    extern __shared__ __align__(16) char dsm[];
    __half* Asm = reinterpret_cast<__half*>(dsm);
    __half* Bsm = reinterpret_cast<__half*>(dsm + A_BYTES);

    const int m0 = blockIdx.y * BM;
    const int n0 = blockIdx.x * BN;
    const int tid = threadIdx.x;
    const int warpId = tid >> 5;          // 0..3
    const int lane = tid & 31;
    const int KT = K / BKg;

    // 4 warps: 2x2 grid of 64x64 warp tiles
    const int row0 = (warpId & 1) * 64;
    const int col0 = (warpId >> 1) * 64;

    wmma::fragment<wmma::accumulator, 16, 16, 16, float> acc[4][4];
#pragma unroll
    for (int i = 0; i < 4; i++)
#pragma unroll
        for (int j = 0; j < 4; j++) wmma::fill_fragment(acc[i][j], 0.f);

    auto load_stage = [&](int slot, int kt) {
        __half* As = Asm + slot * A_STG_H;
        __half* Bs = Bsm + slot * B_STG_H;
        const int k0 = kt * BKg;
#pragma unroll
        for (int j = 0; j < 8; ++j) {            // A: 128x64 = 1024 vec16
            int idx = tid + GT * j;
            int r = idx >> 3, v = idx & 7;
            cp16(As + r * SKA + v * 8,
                 Ag + (size_t)(m0 + r) * K + k0 + v * 8, 16);
        }
#pragma unroll
        for (int j = 0; j < 8; ++j) {            // B: 64x128 = 1024 vec16
            int idx = tid + GT * j;
            int r = idx >> 4, v = idx & 15;
            int col = n0 + v * 8;
            bool ok = (col < N);
            cp16(Bs + r * SKB + v * 8,
                 Bg + (size_t)(k0 + r) * N + (ok ? col : 0), ok ? 16 : 0);
        }
        cp_commit();
    };

    load_stage(0, 0);
    load_stage(1, 1);

    for (int kt = 0; kt < KT; ++kt) {
        cp_wait<1>();
        __syncthreads();
        if (kt + 2 < KT) load_stage((kt + 2) % 3, kt + 2);
        else cp_commit();

        const int slot = kt % 3;
        const __half* Aw = Asm + slot * A_STG_H + row0 * SKA;
        const __half* Bw = Bsm + slot * B_STG_H + col0;

#pragma unroll
        for (int kk = 0; kk < BKg; kk += 16) {
            wmma::fragment<wmma::matrix_a, 16, 16, 16, __half, wmma::row_major> afr[4];
            wmma::fragment<wmma::matrix_b, 16, 16, 16, __half, wmma::row_major> bfr[4];
#pragma unroll
            for (int i = 0; i < 4; i++)
                wmma::load_matrix_sync(afr[i], Aw + (16 * i) * SKA + kk, SKA);
#pragma unroll
            for (int j = 0; j < 4; j++)
                wmma::load_matrix_sync(bfr[j], Bw + kk * SKB + 16 * j, SKB);
#pragma unroll
            for (int i = 0; i < 4; i++)
#pragma unroll
                for (int j = 0; j < 4; j++)
                    wmma::mma_sync(acc[i][j], afr[i], bfr[j], acc[i][j]);
        }
    }
    __syncthreads();

    if (EPI == 0) {
#pragma unroll
        for (int i = 0; i < 4; i++)
#pragma unroll
            for (int j = 0; j < 4; j++)
                wmma::store_matrix_sync(
                    Cf + (size_t)(m0 + row0 + 16 * i) * N + n0 + col0 + 16 * j,
                    acc[i][j], N, wmma::mem_row_major);
        return;
    }

    // staged epilogue via per-warp 16x16 tiles (ld=20)
    float* stage = reinterpret_cast<float*>(dsm) + warpId * (16 * 20);
#pragma unroll
    for (int i = 0; i < 4; i++) {
#pragma unroll
        for (int j = 0; j < 4; j++) {
            wmma::store_matrix_sync(stage, acc[i][j], 20, wmma::mem_row_major);
            __syncwarp();
            if (EPI == 1) {
#pragma unroll
                for (int e = 0; e < 8; ++e) {
                    int idx = lane + 32 * e;
                    int rr = idx >> 4, cc = idx & 15;
                    int row = m0 + row0 + i * 16 + rr;
                    int col = n0 + col0 + j * 16 + cc;
                    if (col < N)
                        Cf[(size_t)row * N + col] = stage[rr * 20 + cc];
                }
            } else {
                // fused gate + yfull, half2 stores (col pairs share h: hd=64)
#pragma unroll
                for (int e = 0; e < 4; ++e) {
                    int p = lane + 32 * e;          // 0..127
                    int rr = p >> 3, pc = p & 7;
                    int row = m0 + row0 + i * 16 + rr;
                    int col = n0 + col0 + j * 16 + 2 * pc;
                    float v0 = stage[rr * 20 + 2 * pc]     + __ldg(&bias[col]);
                    float v1 = stage[rr * 20 + 2 * pc + 1] + __ldg(&bias[col + 1]);
                    float g0 = 1.f / (1.f + __expf(-v0));
                    float g1 = 1.f / (1.f + __expf(-v1));
                    int h = col >> 6;
                    float yv = __ldg(&Y[(size_t)row * Hc + h]);
                    float dp = __ldg(&Dp[h]);
                    __half2 xv = *reinterpret_cast<const __half2*>(
                        xh + (size_t)row * DMc + col);
                    float2 xf = __half22float2(xv);
                    float r0 = (yv + xf.x * dp) * g0;
                    float r1 = (yv + xf.y * dp) * g1;
                    *reinterpret_cast<__half2*>(Ch + (size_t)row * DMc + col) =
                        __floats2half2_rn(r0, r1);
                }
            }
            __syncwarp();
        }
    }
}

// ---------------- segmented scan ----------------
__global__ void __launch_bounds__(128)
scan_pass1(const float* __restrict__ P, const float* __restrict__ Amat,
           float* __restrict__ segstate, float* __restrict__ segdecay) {
    __shared__ float sP[CHk][LDP];
    const int blk = blockIdx.x;              // ((b*H + h)*SEG + seg)
    const int seg = blk & (SEG - 1);
    const int bh = blk >> 3;
    const int b = bh >> 5, h = bh & 31;
    const int n = threadIdx.x;
    const float Ahn = Amat[h * Nc + n];
    const float* Pb = P + ((size_t)b * Lc + seg * LSEG) * LDP;
    float s = 0.f, sumd = 0.f;

    for (int t0 = 0; t0 < LSEG; t0 += CHk) {
        const float4* src = reinterpret_cast<const float4*>(Pb + (size_t)t0 * LDP);
        float4* dst = reinterpret_cast<float4*>(&sP[0][0]);
        for (int i = threadIdx.x; i < CHk * (LDP / 4); i += 128) dst[i] = src[i];
        __syncthreads();
#pragma unroll 4
        for (int i = 0; i < CHk; ++i) {
            float z = sP[i][2 * Nc + h] + sP[i][n];
            float d = __logf(1.f + __expf(z));
            float a = __expf(d * Ahn);
            s = fmaf(a, s, d * d);
            sumd += d;
        }
        __syncthreads();
    }
    segstate[blk * Nc + n] = s;
    segdecay[blk * Nc + n] = __expf(Ahn * sumd);
}

__global__ void scan_pass2(const float* __restrict__ state,
                           const float* __restrict__ decay,
                           float* __restrict__ hin) {
    int i = blockIdx.x * blockDim.x + threadIdx.x;
    if (i >= Bc * Hc * Nc) return;
    int bh = i >> 7, n = i & 127;
    float h = 0.f;
#pragma unroll
    for (int s = 0; s < SEG; s++) {
        int idx = (bh * SEG + s) * Nc + n;
        hin[idx] = h;
        h = decay[idx] * h + state[idx];
    }
}

__global__ void __launch_bounds__(128)
scan_pass3(const float* __restrict__ P, const float* __restrict__ Amat,
           const float* __restrict__ hin, float* __restrict__ Y) {
    __shared__ float sP[CHk][LDP];
    __shared__ float part[4][CHk];
    const int blk = blockIdx.x;
    const int seg = blk & (SEG - 1);
    const int bh = blk >> 3;
    const int b = bh >> 5, h = bh & 31;
    const int n = threadIdx.x;
    const int warp = n >> 5, lane = n & 31;
    const float Ahn = Amat[h * Nc + n];
    const float* Pb = P + ((size_t)b * Lc + seg * LSEG) * LDP;
    float s = hin[blk * Nc + n];

    for (int t0 = 0; t0 < LSEG; t0 += CHk) {
        const float4* src = reinterpret_cast<const float4*>(Pb + (size_t)t0 * LDP);
        float4* dst = reinterpret_cast<float4*>(&sP[0][0]);
        for (int i = threadIdx.x; i < CHk * (LDP / 4); i += 128) dst[i] = src[i];
        __syncthreads();
#pragma unroll 4
        for (int i = 0; i < CHk; ++i) {
            float Bn = sP[i][n];
            float Cn = sP[i][Nc + n];
            float db = sP[i][2 * Nc + h];
            float z = db + Bn;
            float d = __logf(1.f + __expf(z));
            float a = __expf(d * Ahn);
            s = fmaf(a, s, d * d);
            float v = s * Cn;
            v += __shfl_xor_sync(0xffffffffu, v, 16);
            v += __shfl_xor_sync(0xffffffffu, v, 8);
            v += __shfl_xor_sync(0xffffffffu, v, 4);
            v += __shfl_xor_sync(0xffffffffu, v, 2);
            v += __shfl_xor_sync(0xffffffffu, v, 1);
            if (lane == 0) part[warp][i] = v;
        }
        __syncthreads();
        if (threadIdx.x < CHk) {
            float yv = part[0][threadIdx.x] + part[1][threadIdx.x] +
                       part[2][threadIdx.x] + part[3][threadIdx.x];
            Y[(size_t)(b * Lc + seg * LSEG + t0 + threadIdx.x) * Hc + h] = yv;
        }
        __syncthreads();
    }
}

// ---------------- launcher ----------------
extern "C" void kernel_launch(void* const* d_in, const int* in_sizes, int n_in,
                              void* d_out, int out_size) {
    const float* x  = (const float*)d_in[0];
    const float* Wx = (const float*)d_in[1];
    const float* Wg = (const float*)d_in[2];
    const float* bg = (const float*)d_in[3];
    const float* Wo = (const float*)d_in[4];
    const float* Am = (const float*)d_in[5];
    const float* Dp = (const float*)d_in[6];
    float* out = (float*)d_out;

    __half *xh, *Wxh, *Wgh, *Woh, *yfh;
    float *P, *Y, *sst, *sdc, *shn;
    cudaGetSymbolAddress((void**)&xh,  g_xh);
    cudaGetSymbolAddress((void**)&Wxh, g_Wxh);
    cudaGetSymbolAddress((void**)&Wgh, g_Wgh);
    cudaGetSymbolAddress((void**)&Woh, g_Woh);
    cudaGetSymbolAddress((void**)&P,   g_P);
    cudaGetSymbolAddress((void**)&Y,   g_Y);
    cudaGetSymbolAddress((void**)&yfh, g_yf);
    cudaGetSymbolAddress((void**)&sst, g_segstate);
    cudaGetSymbolAddress((void**)&sdc, g_segdecay);
    cudaGetSymbolAddress((void**)&shn, g_seghin);

    cudaFuncSetAttribute(gemm128<0>, cudaFuncAttributeMaxDynamicSharedMemorySize, GEMM_DSMEM);
    cudaFuncSetAttribute(gemm128<1>, cudaFuncAttributeMaxDynamicSharedMemorySize, GEMM_DSMEM);
    cudaFuncSetAttribute(gemm128<2>, cudaFuncAttributeMaxDynamicSharedMemorySize, GEMM_DSMEM);

    const int T = 256;
    const size_t HOFF = (size_t)MH * DMc;     // element offset of upper half

    // --- s0: fused converts ---
    conv_all<<<(C3 + 1023) / 1024, 512>>>(x, Wx, Wg, Wo, xh, Wxh, Wgh, Woh);

    // --- s0: P = x @ Wx (fp32, N edge) ---
    gemm128<1><<<dim3((LDP + BN - 1) / BN, Mrows / BM), GT, GEMM_DSMEM>>>(
        xh, Wxh, P, nullptr, nullptr, nullptr, nullptr, nullptr, LDP, DMc);

    // --- s0: segmented scan -> Y ---
    scan_pass1<<<Bc * Hc * SEG, 128>>>(P, Am, sst, sdc);
    scan_pass2<<<(Bc * Hc * Nc + T - 1) / T, T>>>(sst, sdc, shn);
    scan_pass3<<<Bc * Hc * SEG, 128>>>(P, Am, shn, Y);

    // --- s0: fused gate+yfull GEMM, ladder halves ---
    gemm128<2><<<dim3(DMc / BN, MH / BM), GT, GEMM_DSMEM>>>(
        xh, Wgh, nullptr, yfh, bg, Y, Dp, xh, DMc, DMc);        // yf_lo
    cudaEventRecord(g_ctx.eglo, 0);
    gemm128<2><<<dim3(DMc / BN, MH / BM), GT, GEMM_DSMEM>>>(
        xh + HOFF, Wgh, nullptr, yfh + HOFF, bg,
        Y + (size_t)MH * Hc, Dp, xh + HOFF, DMc, DMc);          // yf_hi

    // --- s1 (forked from s0 via eglo): out_lo, overlaps yf_hi ---
    cudaStreamWaitEvent(g_ctx.s1, g_ctx.eglo, 0);
    gemm128<0><<<dim3(DMc / BN, MH / BM), GT, GEMM_DSMEM, g_ctx.s1>>>(
        yfh, Woh, out, nullptr, nullptr, nullptr, nullptr, nullptr, DMc, DMc);
    cudaEventRecord(g_ctx.eout1, g_ctx.s1);

    // --- s0: out_hi ---
    gemm128<0><<<dim3(DMc / BN, MH / BM), GT, GEMM_DSMEM>>>(
        yfh + HOFF, Woh, out + HOFF, nullptr, nullptr, nullptr, nullptr, nullptr,
        DMc, DMc);

    // join: s0 waits for out_lo
    cudaStreamWaitEvent(0, g_ctx.eout1, 0);
}

// round 15
// speedup vs baseline: 1.0419x; 1.0419x over previous
#include <cuda_runtime.h>
#include <cuda_fp16.h>
#include <mma.h>
#include <cstdint>

using namespace nvcuda;

// ---------------- problem constants ----------------
#define Bc 4
#define Lc 4096
#define DMc 2048
#define Hc 32
#define Nc 128
#define Mrows (Bc * Lc)            // 16384
#define MH (Mrows / 2)             // 8192 (ladder half)
#define LDP (2 * Nc + Hc)          // 288
#define SEG 8
#define LSEG (Lc / SEG)            // 512
#define CHk 32

// ---------------- scratch (device globals; allocation-free) ----------------
__device__ __half g_xh [(size_t)Mrows * DMc];
__device__ __half g_Wxh[(size_t)DMc * LDP];
__device__ __half g_Wgh[(size_t)DMc * DMc];
__device__ __half g_Woh[(size_t)DMc * DMc];
__device__ float  g_P  [(size_t)Mrows * LDP];
__device__ float  g_Y  [(size_t)Mrows * Hc];
__device__ __half g_gate[(size_t)Mrows * DMc];
__device__ __half g_yf [(size_t)Mrows * DMc];
__device__ float  g_segstate[Bc * Hc * SEG * Nc];
__device__ float  g_segdecay[Bc * Hc * SEG * Nc];
__device__ float  g_seghin  [Bc * Hc * SEG * Nc];

// ---------------- side stream + events (host objects, created once) --------
struct StreamCtx {
    cudaStream_t s1;
    cudaEvent_t e0, exB, eg0, escan, edone;
    StreamCtx() {
        cudaStreamCreateWithFlags(&s1, cudaStreamNonBlocking);
        cudaEventCreateWithFlags(&e0,    cudaEventDisableTiming);
        cudaEventCreateWithFlags(&exB,   cudaEventDisableTiming);
        cudaEventCreateWithFlags(&eg0,   cudaEventDisableTiming);
        cudaEventCreateWithFlags(&escan, cudaEventDisableTiming);
        cudaEventCreateWithFlags(&edone, cudaEventDisableTiming);
    }
};
static StreamCtx g_ctx;

// ---------------- cp.async helpers ----------------
__device__ __forceinline__ void cp16(void* smem, const void* gmem, int sz) {
    unsigned s = (unsigned)__cvta_generic_to_shared(smem);
    asm volatile("cp.async.cg.shared.global [%0], [%1], 16, %2;\n"
                 :: "r"(s), "l"(gmem), "r"(sz));
}
__device__ __forceinline__ void cp_commit() {
    asm volatile("cp.async.commit_group;\n");
}
template <int NWAIT>
__device__ __forceinline__ void cp_wait() {
    asm volatile("cp.async.wait_group %0;\n" :: "n"(NWAIT));
}

// ---------------- converts ----------------
// part A: weights (Wx, Wg, Wo) + lower half of x     part B: upper half of x
#define DXLO (MH * DMc / 4)                 // x_lo   4194304
#define DW0  (DXLO + DMc * LDP / 4)         // +Wx     147456
#define DW1  (DW0 + DMc * DMc / 4)          // +Wg    1048576
#define DW2  (DW1 + DMc * DMc / 4)          // +Wo    1048576 -> total A

__device__ __forceinline__ void cv4(const float* __restrict__ src,
                                    __half* __restrict__ dst, int off) {
    float4 v = reinterpret_cast<const float4*>(src)[off];
    __half2 a = __floats2half2_rn(v.x, v.y);
    __half2 b = __floats2half2_rn(v.z, v.w);
    uint2 r;
    r.x = *reinterpret_cast<uint32_t*>(&a);
    r.y = *reinterpret_cast<uint32_t*>(&b);
    reinterpret_cast<uint2*>(dst)[off] = r;
}

__global__ void __launch_bounds__(512)
conv_partA(const float* __restrict__ x,  const float* __restrict__ Wx,
           const float* __restrict__ Wg, const float* __restrict__ Wo,
           __half* __restrict__ xh,  __half* __restrict__ Wxh,
           __half* __restrict__ Wgh, __half* __restrict__ Woh) {
#pragma unroll
    for (int u = 0; u < 2; ++u) {
        int i = blockIdx.x * 1024 + threadIdx.x + u * 512;
        if (i >= DW2) return;
        if (i < DXLO)      cv4(x,  xh,  i);
        else if (i < DW0)  cv4(Wx, Wxh, i - DXLO);
        else if (i < DW1)  cv4(Wg, Wgh, i - DW0);
        else               cv4(Wo, Woh, i - DW1);
    }
}

__global__ void __launch_bounds__(512)
conv_partB(const float* __restrict__ x, __half* __restrict__ xh) {
    // x_hi: second MH rows
#pragma unroll
    for (int u = 0; u < 2; ++u) {
        int i = blockIdx.x * 1024 + threadIdx.x + u * 512;
        if (i < DXLO) cv4(x + (size_t)MH * DMc, xh + (size_t)MH * DMc, i);
    }
}

// ---------------- wmma GEMM: 128x128 tile, 4 warps, 64x64 warp tile --------
// EPI 0: direct fp32 store (N % 128 == 0)
// EPI 1: staged fp32 store with N edge (P GEMM)
// EPI 2: gate: Ch = half(sigmoid(acc + bias[col])), half2 stores
#define BM 128
#define BN 128
#define BKg 64
#define SKA 72
#define SKB 136
#define A_STG_H (BM * SKA)
#define B_STG_H (BKg * SKB)
#define A_BYTES (3 * A_STG_H * 2)
#define GEMM_DSMEM (A_BYTES + 3 * B_STG_H * 2)   // 107520
#define GT 128                                   // threads per GEMM CTA

template <int EPI>
__global__ void __launch_bounds__(GT)
gemm128(const __half* __restrict__ Ag, const __half* __restrict__ Bg,
        float* __restrict__ Cf, __half* __restrict__ Ch,
        const float* __restrict__ bias, int N, int K) {
    extern __shared__ __align__(16) char dsm[];
    __half* Asm = reinterpret_cast<__half*>(dsm);
    __half* Bsm = reinterpret_cast<__half*>(dsm + A_BYTES);

    const int m0 = blockIdx.y * BM;
    const int n0 = blockIdx.x * BN;
    const int tid = threadIdx.x;
    const int warpId = tid >> 5;          // 0..3
    const int lane = tid & 31;
    const int KT = K / BKg;

    // 4 warps: 2x2 grid of 64x64 warp tiles
    const int row0 = (warpId & 1) * 64;
    const int col0 = (warpId >> 1) * 64;

    wmma::fragment<wmma::accumulator, 16, 16, 16, float> acc[4][4];
#pragma unroll
    for (int i = 0; i < 4; i++)
#pragma unroll
        for (int j = 0; j < 4; j++) wmma::fill_fragment(acc[i][j], 0.f);

    auto load_stage = [&](int slot, int kt) {
        __half* As = Asm + slot * A_STG_H;
        __half* Bs = Bsm + slot * B_STG_H;
        const int k0 = kt * BKg;
#pragma unroll
        for (int j = 0; j < 8; ++j) {            // A: 128x64 = 1024 vec16
            int idx = tid + GT * j;
            int r = idx >> 3, v = idx & 7;
            cp16(As + r * SKA + v * 8,
                 Ag + (size_t)(m0 + r) * K + k0 + v * 8, 16);
        }
#pragma unroll
        for (int j = 0; j < 8; ++j) {            // B: 64x128 = 1024 vec16
            int idx = tid + GT * j;
            int r = idx >> 4, v = idx & 15;
            int col = n0 + v * 8;
            bool ok = (col < N);
            cp16(Bs + r * SKB + v * 8,
                 Bg + (size_t)(k0 + r) * N + (ok ? col : 0), ok ? 16 : 0);
        }
        cp_commit();
    };

    load_stage(0, 0);
    load_stage(1, 1);

    for (int kt = 0; kt < KT; ++kt) {
        cp_wait<1>();
        __syncthreads();
        if (kt + 2 < KT) load_stage((kt + 2) % 3, kt + 2);
        else cp_commit();

        const int slot = kt % 3;
        const __half* Aw = Asm + slot * A_STG_H + row0 * SKA;
        const __half* Bw = Bsm + slot * B_STG_H + col0;

#pragma unroll
        for (int kk = 0; kk < BKg; kk += 16) {
            wmma::fragment<wmma::matrix_a, 16, 16, 16, __half, wmma::row_major> afr[4];
            wmma::fragment<wmma::matrix_b, 16, 16, 16, __half, wmma::row_major> bfr[4];
#pragma unroll
            for (int i = 0; i < 4; i++)
                wmma::load_matrix_sync(afr[i], Aw + (16 * i) * SKA + kk, SKA);
#pragma unroll
            for (int j = 0; j < 4; j++)
                wmma::load_matrix_sync(bfr[j], Bw + kk * SKB + 16 * j, SKB);
#pragma unroll
            for (int i = 0; i < 4; i++)
#pragma unroll
                for (int j = 0; j < 4; j++)
                    wmma::mma_sync(acc[i][j], afr[i], bfr[j], acc[i][j]);
        }
    }
    __syncthreads();

    if (EPI == 0) {
#pragma unroll
        for (int i = 0; i < 4; i++)
#pragma unroll
            for (int j = 0; j < 4; j++)
                wmma::store_matrix_sync(
                    Cf + (size_t)(m0 + row0 + 16 * i) * N + n0 + col0 + 16 * j,
                    acc[i][j], N, wmma::mem_row_major);
        return;
    }

    // staged epilogue via per-warp 16x16 tiles (ld=20)
    float* stage = reinterpret_cast<float*>(dsm) + warpId * (16 * 20);
#pragma unroll
    for (int i = 0; i < 4; i++) {
#pragma unroll
        for (int j = 0; j < 4; j++) {
            wmma::store_matrix_sync(stage, acc[i][j], 20, wmma::mem_row_major);
            __syncwarp();
            if (EPI == 1) {
#pragma unroll
                for (int e = 0; e < 8; ++e) {
                    int idx = lane + 32 * e;
                    int rr = idx >> 4, cc = idx & 15;
                    int row = m0 + row0 + i * 16 + rr;
                    int col = n0 + col0 + j * 16 + cc;
                    if (col < N)
                        Cf[(size_t)row * N + col] = stage[rr * 20 + cc];
                }
            } else {
                // vectorized half2 gate stores
#pragma unroll
                for (int e = 0; e < 4; ++e) {
                    int p = lane + 32 * e;          // 0..127
                    int rr = p >> 3, pc = p & 7;
                    int row = m0 + row0 + i * 16 + rr;
                    int col = n0 + col0 + j * 16 + 2 * pc;
                    float v0 = stage[rr * 20 + 2 * pc]     + __ldg(&bias[col]);
                    float v1 = stage[rr * 20 + 2 * pc + 1] + __ldg(&bias[col + 1]);
                    float g0 = 1.f / (1.f + __expf(-v0));
                    float g1 = 1.f / (1.f + __expf(-v1));
                    *reinterpret_cast<__half2*>(Ch + (size_t)row * N + col) =
                        __floats2half2_rn(g0, g1);
                }
            }
            __syncwarp();
        }
    }
}

// ---------------- segmented scan ----------------
__global__ void __launch_bounds__(128)
scan_pass1(const float* __restrict__ P, const float* __restrict__ Amat,
           float* __restrict__ segstate, float* __restrict__ segdecay) {
    __shared__ float sP[CHk][LDP];
    const int blk = blockIdx.x;              // ((b*H + h)*SEG + seg)
    const int seg = blk & (SEG - 1);
    const int bh = blk >> 3;
    const int b = bh >> 5, h = bh & 31;
    const int n = threadIdx.x;
    const float Ahn = Amat[h * Nc + n];
    const float* Pb = P + ((size_t)b * Lc + seg * LSEG) * LDP;
    float s = 0.f, sumd = 0.f;

    for (int t0 = 0; t0 < LSEG; t0 += CHk) {
        const float4* src = reinterpret_cast<const float4*>(Pb + (size_t)t0 * LDP);
        float4* dst = reinterpret_cast<float4*>(&sP[0][0]);
        for (int i = threadIdx.x; i < CHk * (LDP / 4); i += 128) dst[i] = src[i];
        __syncthreads();
#pragma unroll 4
        for (int i = 0; i < CHk; ++i) {
            float z = sP[i][2 * Nc + h] + sP[i][n];
            float d = __logf(1.f + __expf(z));
            float a = __expf(d * Ahn);
            s = fmaf(a, s, d * d);
            sumd += d;
        }
        __syncthreads();
    }
    segstate[blk * Nc + n] = s;
    segdecay[blk * Nc + n] = __expf(Ahn * sumd);
}

__global__ void scan_pass2(const float* __restrict__ state,
                           const float* __restrict__ decay,
                           float* __restrict__ hin) {
    int i = blockIdx.x * blockDim.x + threadIdx.x;
    if (i >= Bc * Hc * Nc) return;
    int bh = i >> 7, n = i & 127;
    float h = 0.f;
#pragma unroll
    for (int s = 0; s < SEG; s++) {
        int idx = (bh * SEG + s) * Nc + n;
        hin[idx] = h;
        h = decay[idx] * h + state[idx];
    }
}

__global__ void __launch_bounds__(128)
scan_pass3(const float* __restrict__ P, const float* __restrict__ Amat,
           const float* __restrict__ hin, float* __restrict__ Y) {
    __shared__ float sP[CHk][LDP];
    __shared__ float part[4][CHk];
    const int blk = blockIdx.x;
    const int seg = blk & (SEG - 1);
    const int bh = blk >> 3;
    const int b = bh >> 5, h = bh & 31;
    const int n = threadIdx.x;
    const int warp = n >> 5, lane = n & 31;
    const float Ahn = Amat[h * Nc + n];
    const float* Pb = P + ((size_t)b * Lc + seg * LSEG) * LDP;
    float s = hin[blk * Nc + n];

    for (int t0 = 0; t0 < LSEG; t0 += CHk) {
        const float4* src = reinterpret_cast<const float4*>(Pb + (size_t)t0 * LDP);
        float4* dst = reinterpret_cast<float4*>(&sP[0][0]);
        for (int i = threadIdx.x; i < CHk * (LDP / 4); i += 128) dst[i] = src[i];
        __syncthreads();
#pragma unroll 4
        for (int i = 0; i < CHk; ++i) {
            float Bn = sP[i][n];
            float Cn = sP[i][Nc + n];
            float db = sP[i][2 * Nc + h];
            float z = db + Bn;
            float d = __logf(1.f + __expf(z));
            float a = __expf(d * Ahn);
            s = fmaf(a, s, d * d);
            float v = s * Cn;
            v += __shfl_xor_sync(0xffffffffu, v, 16);
            v += __shfl_xor_sync(0xffffffffu, v, 8);
            v += __shfl_xor_sync(0xffffffffu, v, 4);
            v += __shfl_xor_sync(0xffffffffu, v, 2);
            v += __shfl_xor_sync(0xffffffffu, v, 1);
            if (lane == 0) part[warp][i] = v;
        }
        __syncthreads();
        if (threadIdx.x < CHk) {
            float yv = part[0][threadIdx.x] + part[1][threadIdx.x] +
                       part[2][threadIdx.x] + part[3][threadIdx.x];
            Y[(size_t)(b * Lc + seg * LSEG + t0 + threadIdx.x) * Hc + h] = yv;
        }
        __syncthreads();
    }
}

// ---------------- y_full assembly (operates on a row-range) ----------------
__global__ void yfull_kernel(const __half* __restrict__ xh,
                             const __half* __restrict__ gate,
                             const float* __restrict__ Y,
                             const float* __restrict__ Dp,
                             __half* __restrict__ yf, int n2) {
    int i = blockIdx.x * blockDim.x + threadIdx.x;   // over rows*DM/2 half2
    if (i >= n2) return;
    int m = i >> 10;
    int kk = i & 1023;
    int h = kk >> 5;
    float yv = __ldg(&Y[m * Hc + h]);
    float dp = __ldg(&Dp[h]);
    __half2 xv = reinterpret_cast<const __half2*>(xh)[i];
    __half2 gv = reinterpret_cast<const __half2*>(gate)[i];
    float2 xf = __half22float2(xv);
    float2 gf = __half22float2(gv);
    float r0 = (yv + xf.x * dp) * gf.x;
    float r1 = (yv + xf.y * dp) * gf.y;
    reinterpret_cast<__half2*>(yf)[i] = __floats2half2_rn(r0, r1);
}

// ---------------- launcher ----------------
extern "C" void kernel_launch(void* const* d_in, const int* in_sizes, int n_in,
                              void* d_out, int out_size) {
    const float* x  = (const float*)d_in[0];
    const float* Wx = (const float*)d_in[1];
    const float* Wg = (const float*)d_in[2];
    const float* bg = (const float*)d_in[3];
    const float* Wo = (const float*)d_in[4];
    const float* Am = (const float*)d_in[5];
    const float* Dp = (const float*)d_in[6];
    float* out = (float*)d_out;

    __half *xh, *Wxh, *Wgh, *Woh, *gateh, *yfh;
    float *P, *Y, *sst, *sdc, *shn;
    cudaGetSymbolAddress((void**)&xh,  g_xh);
    cudaGetSymbolAddress((void**)&Wxh, g_Wxh);
    cudaGetSymbolAddress((void**)&Wgh, g_Wgh);
    cudaGetSymbolAddress((void**)&Woh, g_Woh);
    cudaGetSymbolAddress((void**)&P,   g_P);
    cudaGetSymbolAddress((void**)&Y,   g_Y);
    cudaGetSymbolAddress((void**)&gateh, g_gate);
    cudaGetSymbolAddress((void**)&yfh, g_yf);
    cudaGetSymbolAddress((void**)&sst, g_segstate);
    cudaGetSymbolAddress((void**)&sdc, g_segdecay);
    cudaGetSymbolAddress((void**)&shn, g_seghin);

    cudaFuncSetAttribute(gemm128<0>, cudaFuncAttributeMaxDynamicSharedMemorySize, GEMM_DSMEM);
    cudaFuncSetAttribute(gemm128<1>, cudaFuncAttributeMaxDynamicSharedMemorySize, GEMM_DSMEM);
    cudaFuncSetAttribute(gemm128<2>, cudaFuncAttributeMaxDynamicSharedMemorySize, GEMM_DSMEM);

    const int T = 256;
    const size_t HOFF = (size_t)MH * DMc;     // element offset of upper half

    // --- s0: convert part A (weights + x_lo), then part B (x_hi) ---
    conv_partA<<<(DW2 + 1023) / 1024, 512>>>(x, Wx, Wg, Wo, xh, Wxh, Wgh, Woh);
    cudaEventRecord(g_ctx.e0, 0);
    conv_partB<<<(DXLO + 1023) / 1024, 512>>>(x, xh);
    cudaEventRecord(g_ctx.exB, 0);

    // --- s0: P = x @ Wx (fp32, N edge) ---
    gemm128<1><<<dim3((LDP + BN - 1) / BN, Mrows / BM), GT, GEMM_DSMEM>>>(
        xh, Wxh, P, nullptr, nullptr, LDP, DMc);

    // --- s0: segmented scan -> Y ---
    scan_pass1<<<Bc * Hc * SEG, 128>>>(P, Am, sst, sdc);
    scan_pass2<<<(Bc * Hc * Nc + T - 1) / T, T>>>(sst, sdc, shn);
    scan_pass3<<<Bc * Hc * SEG, 128>>>(P, Am, shn, Y);
    cudaEventRecord(g_ctx.escan, 0);

    // --- s1: gate GEMM in two M-halves (gate_lo starts right after part A) ---
    cudaStreamWaitEvent(g_ctx.s1, g_ctx.e0, 0);
    gemm128<2><<<dim3(DMc / BN, MH / BM), GT, GEMM_DSMEM, g_ctx.s1>>>(
        xh, Wgh, nullptr, gateh, bg, DMc, DMc);                 // gate_lo
    cudaEventRecord(g_ctx.eg0, g_ctx.s1);
    cudaStreamWaitEvent(g_ctx.s1, g_ctx.exB, 0);
    gemm128<2><<<dim3(DMc / BN, MH / BM), GT, GEMM_DSMEM, g_ctx.s1>>>(
        xh + HOFF, Wgh, nullptr, gateh + HOFF, bg, DMc, DMc);   // gate_hi

    // --- s0: lower-half tail (overlaps gate_hi) ---
    cudaStreamWaitEvent(0, g_ctx.eg0, 0);
    {
        int n2 = MH * (DMc / 2);
        yfull_kernel<<<(n2 + T - 1) / T, T>>>(xh, gateh, Y, Dp, yfh, n2);
    }
    gemm128<0><<<dim3(DMc / BN, MH / BM), GT, GEMM_DSMEM>>>(
        yfh, Woh, out, nullptr, nullptr, DMc, DMc);             // out_lo

    // --- s1: upper-half tail ---
    cudaStreamWaitEvent(g_ctx.s1, g_ctx.escan, 0);
    {
        int n2 = MH * (DMc / 2);
        yfull_kernel<<<(n2 + T - 1) / T, T, 0, g_ctx.s1>>>(
            xh + HOFF, gateh + HOFF, Y + (size_t)MH * Hc, Dp, yfh + HOFF, n2);
    }
    gemm128<0><<<dim3(DMc / BN, MH / BM), GT, GEMM_DSMEM, g_ctx.s1>>>(
        yfh + HOFF, Woh, out + HOFF, nullptr, nullptr, DMc, DMc);  // out_hi
    cudaEventRecord(g_ctx.edone, g_ctx.s1);

    // join: everything returns to the main stream
    cudaStreamWaitEvent(0, g_ctx.edone, 0);
}

// round 16
// speedup vs baseline: 1.1114x; 1.0667x over previous
#include <cuda_runtime.h>
#include <cuda_fp16.h>
#include <mma.h>
#include <cstdint>

using namespace nvcuda;

// ---------------- problem constants ----------------
#define Bc 4
#define Lc 4096
#define DMc 2048
#define Hc 32
#define Nc 128
#define Mrows (Bc * Lc)            // 16384
#define MH (Mrows / 2)             // 8192 (pipeline half)
#define LDP (2 * Nc + Hc)          // 288
#define SEG 8
#define LSEG (Lc / SEG)            // 512
#define CHk 32
#define CH1 64

// ---------------- scratch (device globals; allocation-free) ----------------
__device__ __half g_xh [(size_t)Mrows * DMc];
__device__ __half g_Wxh[(size_t)DMc * LDP];
__device__ __half g_Wgh[(size_t)DMc * DMc];
__device__ __half g_Woh[(size_t)DMc * DMc];
__device__ float  g_P  [(size_t)Mrows * LDP];
__device__ float  g_Y  [(size_t)Mrows * Hc];
__device__ __half g_gate[(size_t)Mrows * DMc];
__device__ __half g_yf [(size_t)Mrows * DMc];
__device__ float  g_segstate[Bc * Hc * SEG * Nc];
__device__ float  g_segdecay[Bc * Hc * SEG * Nc];
__device__ float  g_seghin  [Bc * Hc * SEG * Nc];

// ---------------- side stream + events (host objects, created once) --------
struct StreamCtx {
    cudaStream_t s1;
    cudaEvent_t e0, eg0, escan, edone;
    StreamCtx() {
        cudaStreamCreateWithFlags(&s1, cudaStreamNonBlocking);
        cudaEventCreateWithFlags(&e0,    cudaEventDisableTiming);
        cudaEventCreateWithFlags(&eg0,   cudaEventDisableTiming);
        cudaEventCreateWithFlags(&escan, cudaEventDisableTiming);
        cudaEventCreateWithFlags(&edone, cudaEventDisableTiming);
    }
};
static StreamCtx g_ctx;

// ---------------- cp.async helpers ----------------
__device__ __forceinline__ void cp16(void* smem, const void* gmem, int sz) {
    unsigned s = (unsigned)__cvta_generic_to_shared(smem);
    asm volatile("cp.async.cg.shared.global [%0], [%1], 16, %2;\n"
                 :: "r"(s), "l"(gmem), "r"(sz));
}
__device__ __forceinline__ void cp_commit() {
    asm volatile("cp.async.commit_group;\n");
}
template <int NWAIT>
__device__ __forceinline__ void cp_wait() {
    asm volatile("cp.async.wait_group %0;\n" :: "n"(NWAIT));
}

// ---------------- fused convert: x, Wx, Wg, Wo -> fp16 ----------------
#define C0 (Mrows * DMc / 4)               // x      8388608
#define C1 (C0 + DMc * LDP / 4)            // +Wx     147456
#define C2 (C1 + DMc * DMc / 4)            // +Wg    1048576
#define C3 (C2 + DMc * DMc / 4)            // +Wo    1048576

__device__ __forceinline__ void conv_one(
    int i, const float* __restrict__ x,  const float* __restrict__ Wx,
    const float* __restrict__ Wg, const float* __restrict__ Wo,
    __half* __restrict__ xh,  __half* __restrict__ Wxh,
    __half* __restrict__ Wgh, __half* __restrict__ Woh) {
    const float* src; __half* dst; int off;
    if (i < C0)      { src = x;  dst = xh;  off = i; }
    else if (i < C1) { src = Wx; dst = Wxh; off = i - C0; }
    else if (i < C2) { src = Wg; dst = Wgh; off = i - C1; }
    else             { src = Wo; dst = Woh; off = i - C2; }
    float4 v = reinterpret_cast<const float4*>(src)[off];
    __half2 a = __floats2half2_rn(v.x, v.y);
    __half2 b = __floats2half2_rn(v.z, v.w);
    uint2 r;
    r.x = *reinterpret_cast<uint32_t*>(&a);
    r.y = *reinterpret_cast<uint32_t*>(&b);
    reinterpret_cast<uint2*>(dst)[off] = r;
}

__global__ void __launch_bounds__(512)
conv_all(const float* __restrict__ x,  const float* __restrict__ Wx,
         const float* __restrict__ Wg, const float* __restrict__ Wo,
         __half* __restrict__ xh,  __half* __restrict__ Wxh,
         __half* __restrict__ Wgh, __half* __restrict__ Woh) {
    int base = blockIdx.x * 1024 + threadIdx.x;
    if (base < C3)       conv_one(base,       x, Wx, Wg, Wo, xh, Wxh, Wgh, Woh);
    if (base + 512 < C3) conv_one(base + 512, x, Wx, Wg, Wo, xh, Wxh, Wgh, Woh);
}

// ---------------- wmma GEMM: 128x128 tile, 4 warps, 64x64 warp tile --------
// EPI 0: direct fp32 store (N % 128 == 0)
// EPI 1: staged fp32 store with N edge (P GEMM)
// EPI 2: gate: Ch = half(sigmoid(acc + bias[col])), half2 stores
#define BM 128
#define BN 128
#define BKg 64
#define SKA 72
#define SKB 136
#define A_STG_H (BM * SKA)
#define B_STG_H (BKg * SKB)
#define A_BYTES (3 * A_STG_H * 2)
#define GEMM_DSMEM (A_BYTES + 3 * B_STG_H * 2)   // 107520
#define GT 128                                   // threads per GEMM CTA

template <int EPI>
__global__ void __launch_bounds__(GT)
gemm128(const __half* __restrict__ Ag, const __half* __restrict__ Bg,
        float* __restrict__ Cf, __half* __restrict__ Ch,
        const float* __restrict__ bias, int N, int K) {
    extern __shared__ __align__(16) char dsm[];
    __half* Asm = reinterpret_cast<__half*>(dsm);
    __half* Bsm = reinterpret_cast<__half*>(dsm + A_BYTES);

    const int m0 = blockIdx.y * BM;
    const int n0 = blockIdx.x * BN;
    const int tid = threadIdx.x;
    const int warpId = tid >> 5;          // 0..3
    const int lane = tid & 31;
    const int KT = K / BKg;

    // 4 warps: 2x2 grid of 64x64 warp tiles
    const int row0 = (warpId & 1) * 64;
    const int col0 = (warpId >> 1) * 64;

    wmma::fragment<wmma::accumulator, 16, 16, 16, float> acc[4][4];
#pragma unroll
    for (int i = 0; i < 4; i++)
#pragma unroll
        for (int j = 0; j < 4; j++) wmma::fill_fragment(acc[i][j], 0.f);

    auto load_stage = [&](int slot, int kt) {
        __half* As = Asm + slot * A_STG_H;
        __half* Bs = Bsm + slot * B_STG_H;
        const int k0 = kt * BKg;
#pragma unroll
        for (int j = 0; j < 8; ++j) {            // A: 128x64 = 1024 vec16
            int idx = tid + GT * j;
            int r = idx >> 3, v = idx & 7;
            cp16(As + r * SKA + v * 8,
                 Ag + (size_t)(m0 + r) * K + k0 + v * 8, 16);
        }
#pragma unroll
        for (int j = 0; j < 8; ++j) {            // B: 64x128 = 1024 vec16
            int idx = tid + GT * j;
            int r = idx >> 4, v = idx & 15;
            int col = n0 + v * 8;
            bool ok = (col < N);
            cp16(Bs + r * SKB + v * 8,
                 Bg + (size_t)(k0 + r) * N + (ok ? col : 0), ok ? 16 : 0);
        }
        cp_commit();
    };

    load_stage(0, 0);
    load_stage(1, 1);

    for (int kt = 0; kt < KT; ++kt) {
        cp_wait<1>();
        __syncthreads();
        if (kt + 2 < KT) load_stage((kt + 2) % 3, kt + 2);
        else cp_commit();

        const int slot = kt % 3;
        const __half* Aw = Asm + slot * A_STG_H + row0 * SKA;
        const __half* Bw = Bsm + slot * B_STG_H + col0;

#pragma unroll
        for (int kk = 0; kk < BKg; kk += 16) {
            wmma::fragment<wmma::matrix_a, 16, 16, 16, __half, wmma::row_major> afr[4];
            wmma::fragment<wmma::matrix_b, 16, 16, 16, __half, wmma::row_major> bfr[4];
#pragma unroll
            for (int i = 0; i < 4; i++)
                wmma::load_matrix_sync(afr[i], Aw + (16 * i) * SKA + kk, SKA);
#pragma unroll
            for (int j = 0; j < 4; j++)
                wmma::load_matrix_sync(bfr[j], Bw + kk * SKB + 16 * j, SKB);
#pragma unroll
            for (int i = 0; i < 4; i++)
#pragma unroll
                for (int j = 0; j < 4; j++)
                    wmma::mma_sync(acc[i][j], afr[i], bfr[j], acc[i][j]);
        }
    }
    __syncthreads();

    if (EPI == 0) {
#pragma unroll
        for (int i = 0; i < 4; i++)
#pragma unroll
            for (int j = 0; j < 4; j++)
                wmma::store_matrix_sync(
                    Cf + (size_t)(m0 + row0 + 16 * i) * N + n0 + col0 + 16 * j,
                    acc[i][j], N, wmma::mem_row_major);
        return;
    }

    // staged epilogue via per-warp 16x16 tiles (ld=20)
    float* stage = reinterpret_cast<float*>(dsm) + warpId * (16 * 20);
#pragma unroll
    for (int i = 0; i < 4; i++) {
#pragma unroll
        for (int j = 0; j < 4; j++) {
            wmma::store_matrix_sync(stage, acc[i][j], 20, wmma::mem_row_major);
            __syncwarp();
            if (EPI == 1) {
#pragma unroll
                for (int e = 0; e < 8; ++e) {
                    int idx = lane + 32 * e;
                    int rr = idx >> 4, cc = idx & 15;
                    int row = m0 + row0 + i * 16 + rr;
                    int col = n0 + col0 + j * 16 + cc;
                    if (col < N)
                        Cf[(size_t)row * N + col] = stage[rr * 20 + cc];
                }
            } else {
                // vectorized half2 gate stores
#pragma unroll
                for (int e = 0; e < 4; ++e) {
                    int p = lane + 32 * e;          // 0..127
                    int rr = p >> 3, pc = p & 7;
                    int row = m0 + row0 + i * 16 + rr;
                    int col = n0 + col0 + j * 16 + 2 * pc;
                    float v0 = stage[rr * 20 + 2 * pc]     + __ldg(&bias[col]);
                    float v1 = stage[rr * 20 + 2 * pc + 1] + __ldg(&bias[col + 1]);
                    float g0 = 1.f / (1.f + __expf(-v0));
                    float g1 = 1.f / (1.f + __expf(-v1));
                    *reinterpret_cast<__half2*>(Ch + (size_t)row * N + col) =
                        __floats2half2_rn(g0, g1);
                }
            }
            __syncwarp();
        }
    }
}

// ---------------- segmented scan ----------------
// pass 1 (lean staging): only B columns + own-h db; CH1=64 rows per chunk
__global__ void __launch_bounds__(128)
scan_pass1(const float* __restrict__ P, const float* __restrict__ Amat,
           float* __restrict__ segstate, float* __restrict__ segdecay) {
    __shared__ float sP[CH1][132];           // [.,0..127]=B, [.,128]=db
    const int blk = blockIdx.x;              // ((b*H + h)*SEG + seg)
    const int seg = blk & (SEG - 1);
    const int bh = blk >> 3;
    const int b = bh >> 5, h = bh & 31;
    const int n = threadIdx.x;
    const float Ahn = Amat[h * Nc + n];
    const float* Pb = P + ((size_t)b * Lc + seg * LSEG) * LDP;
    float s = 0.f, sumd = 0.f;

    for (int t0 = 0; t0 < LSEG; t0 += CH1) {
        // stage B cols: CH1 rows x 32 float4
#pragma unroll
        for (int i = threadIdx.x; i < CH1 * 32; i += 128) {
            int row = i >> 5, v = i & 31;
            float4 val = *reinterpret_cast<const float4*>(
                Pb + (size_t)(t0 + row) * LDP + v * 4);
            *reinterpret_cast<float4*>(&sP[row][v * 4]) = val;
        }
        // stage own-h db column
        if (threadIdx.x < CH1)
            sP[threadIdx.x][128] = Pb[(size_t)(t0 + threadIdx.x) * LDP + 2 * Nc + h];
        __syncthreads();
#pragma unroll 4
        for (int i = 0; i < CH1; ++i) {
            float z = sP[i][128] + sP[i][n];
            float d = __logf(1.f + __expf(z));
            float a = __expf(d * Ahn);
            s = fmaf(a, s, d * d);
            sumd += d;
        }
        __syncthreads();
    }
    segstate[blk * Nc + n] = s;
    segdecay[blk * Nc + n] = __expf(Ahn * sumd);
}

__global__ void scan_pass2(const float* __restrict__ state,
                           const float* __restrict__ decay,
                           float* __restrict__ hin) {
    int i = blockIdx.x * blockDim.x + threadIdx.x;
    if (i >= Bc * Hc * Nc) return;
    int bh = i >> 7, n = i & 127;
    float h = 0.f;
#pragma unroll
    for (int s = 0; s < SEG; s++) {
        int idx = (bh * SEG + s) * Nc + n;
        hin[idx] = h;
        h = decay[idx] * h + state[idx];
    }
}

// pass 3 (lean staging): B + C columns + own-h db (260 floats/row)
__global__ void __launch_bounds__(128)
scan_pass3(const float* __restrict__ P, const float* __restrict__ Amat,
           const float* __restrict__ hin, float* __restrict__ Y) {
    __shared__ float sP[CHk][260];           // [.,0..255]=B,C  [.,256]=db
    __shared__ float part[4][CHk];
    const int blk = blockIdx.x;
    const int seg = blk & (SEG - 1);
    const int bh = blk >> 3;
    const int b = bh >> 5, h = bh & 31;
    const int n = threadIdx.x;
    const int warp = n >> 5, lane = n & 31;
    const float Ahn = Amat[h * Nc + n];
    const float* Pb = P + ((size_t)b * Lc + seg * LSEG) * LDP;
    float s = hin[blk * Nc + n];

    for (int t0 = 0; t0 < LSEG; t0 += CHk) {
        // stage B+C cols: CHk rows x 64 float4
#pragma unroll
        for (int i = threadIdx.x; i < CHk * 64; i += 128) {
            int row = i >> 6, v = i & 63;
            float4 val = *reinterpret_cast<const float4*>(
                Pb + (size_t)(t0 + row) * LDP + v * 4);
            *reinterpret_cast<float4*>(&sP[row][v * 4]) = val;
        }
        if (threadIdx.x < CHk)
            sP[threadIdx.x][256] = Pb[(size_t)(t0 + threadIdx.x) * LDP + 2 * Nc + h];
        __syncthreads();
#pragma unroll 4
        for (int i = 0; i < CHk; ++i) {
            float Bn = sP[i][n];
            float Cn = sP[i][Nc + n];
            float z = sP[i][256] + Bn;
            float d = __logf(1.f + __expf(z));
            float a = __expf(d * Ahn);
            s = fmaf(a, s, d * d);
            float v = s * Cn;
            v += __shfl_xor_sync(0xffffffffu, v, 16);
            v += __shfl_xor_sync(0xffffffffu, v, 8);
            v += __shfl_xor_sync(0xffffffffu, v, 4);
            v += __shfl_xor_sync(0xffffffffu, v, 2);
            v += __shfl_xor_sync(0xffffffffu, v, 1);
            if (lane == 0) part[warp][i] = v;
        }
        __syncthreads();
        if (threadIdx.x < CHk) {
            float yv = part[0][threadIdx.x] + part[1][threadIdx.x] +
                       part[2][threadIdx.x] + part[3][threadIdx.x];
            Y[(size_t)(b * Lc + seg * LSEG + t0 + threadIdx.x) * Hc + h] = yv;
        }
        __syncthreads();
    }
}

// ---------------- y_full assembly (operates on a row-range) ----------------
__global__ void yfull_kernel(const __half* __restrict__ xh,
                             const __half* __restrict__ gate,
                             const float* __restrict__ Y,
                             const float* __restrict__ Dp,
                             __half* __restrict__ yf, int n2) {
    int i = blockIdx.x * blockDim.x + threadIdx.x;   // over rows*DM/2 half2
    if (i >= n2) return;
    int m = i >> 10;
    int kk = i & 1023;
    int h = kk >> 5;
    float yv = __ldg(&Y[m * Hc + h]);
    float dp = __ldg(&Dp[h]);
    __half2 xv = reinterpret_cast<const __half2*>(xh)[i];
    __half2 gv = reinterpret_cast<const __half2*>(gate)[i];
    float2 xf = __half22float2(xv);
    float2 gf = __half22float2(gv);
    float r0 = (yv + xf.x * dp) * gf.x;
    float r1 = (yv + xf.y * dp) * gf.y;
    reinterpret_cast<__half2*>(yf)[i] = __floats2half2_rn(r0, r1);
}

// ---------------- launcher ----------------
extern "C" void kernel_launch(void* const* d_in, const int* in_sizes, int n_in,
                              void* d_out, int out_size) {
    const float* x  = (const float*)d_in[0];
    const float* Wx = (const float*)d_in[1];
    const float* Wg = (const float*)d_in[2];
    const float* bg = (const float*)d_in[3];
    const float* Wo = (const float*)d_in[4];
    const float* Am = (const float*)d_in[5];
    const float* Dp = (const float*)d_in[6];
    float* out = (float*)d_out;

    __half *xh, *Wxh, *Wgh, *Woh, *gateh, *yfh;
    float *P, *Y, *sst, *sdc, *shn;
    cudaGetSymbolAddress((void**)&xh,  g_xh);
    cudaGetSymbolAddress((void**)&Wxh, g_Wxh);
    cudaGetSymbolAddress((void**)&Wgh, g_Wgh);
    cudaGetSymbolAddress((void**)&Woh, g_Woh);
    cudaGetSymbolAddress((void**)&P,   g_P);
    cudaGetSymbolAddress((void**)&Y,   g_Y);
    cudaGetSymbolAddress((void**)&gateh, g_gate);
    cudaGetSymbolAddress((void**)&yfh, g_yf);
    cudaGetSymbolAddress((void**)&sst, g_segstate);
    cudaGetSymbolAddress((void**)&sdc, g_segdecay);
    cudaGetSymbolAddress((void**)&shn, g_seghin);

    cudaFuncSetAttribute(gemm128<0>, cudaFuncAttributeMaxDynamicSharedMemorySize, GEMM_DSMEM);
    cudaFuncSetAttribute(gemm128<1>, cudaFuncAttributeMaxDynamicSharedMemorySize, GEMM_DSMEM);
    cudaFuncSetAttribute(gemm128<2>, cudaFuncAttributeMaxDynamicSharedMemorySize, GEMM_DSMEM);

    const int T = 256;
    const size_t HOFF = (size_t)MH * DMc;     // element offset of upper half

    // --- main stream (s0): conv -> P -> scan chain ---
    conv_all<<<(C3 + 1023) / 1024, 512>>>(x, Wx, Wg, Wo, xh, Wxh, Wgh, Woh);
    cudaEventRecord(g_ctx.e0, 0);

    gemm128<1><<<dim3((LDP + BN - 1) / BN, Mrows / BM), GT, GEMM_DSMEM>>>(
        xh, Wxh, P, nullptr, nullptr, LDP, DMc);

    scan_pass1<<<Bc * Hc * SEG, 128>>>(P, Am, sst, sdc);
    scan_pass2<<<(Bc * Hc * Nc + T - 1) / T, T>>>(sst, sdc, shn);
    scan_pass3<<<Bc * Hc * SEG, 128>>>(P, Am, shn, Y);
    cudaEventRecord(g_ctx.escan, 0);

    // --- side stream (s1): gate GEMM in two M-halves ---
    cudaStreamWaitEvent(g_ctx.s1, g_ctx.e0, 0);
    gemm128<2><<<dim3(DMc / BN, MH / BM), GT, GEMM_DSMEM, g_ctx.s1>>>(
        xh, Wgh, nullptr, gateh, bg, DMc, DMc);                 // gate_lo
    cudaEventRecord(g_ctx.eg0, g_ctx.s1);
    gemm128<2><<<dim3(DMc / BN, MH / BM), GT, GEMM_DSMEM, g_ctx.s1>>>(
        xh + HOFF, Wgh, nullptr, gateh + HOFF, bg, DMc, DMc);   // gate_hi

    // --- main stream: lower-half tail (overlaps gate_hi) ---
    cudaStreamWaitEvent(0, g_ctx.eg0, 0);
    {
        int n2 = MH * (DMc / 2);
        yfull_kernel<<<(n2 + T - 1) / T, T>>>(xh, gateh, Y, Dp, yfh, n2);
    }
    gemm128<0><<<dim3(DMc / BN, MH / BM), GT, GEMM_DSMEM>>>(
        yfh, Woh, out, nullptr, nullptr, DMc, DMc);             // out_lo

    // --- side stream: upper-half tail ---
    cudaStreamWaitEvent(g_ctx.s1, g_ctx.escan, 0);
    {
        int n2 = MH * (DMc / 2);
        yfull_kernel<<<(n2 + T - 1) / T, T, 0, g_ctx.s1>>>(
            xh + HOFF, gateh + HOFF, Y + (size_t)MH * Hc, Dp, yfh + HOFF, n2);
    }
    gemm128<0><<<dim3(DMc / BN, MH / BM), GT, GEMM_DSMEM, g_ctx.s1>>>(
        yfh + HOFF, Woh, out + HOFF, nullptr, nullptr, DMc, DMc);  // out_hi
    cudaEventRecord(g_ctx.edone, g_ctx.s1);

    // join: everything returns to the main stream
    cudaStreamWaitEvent(0, g_ctx.edone, 0);
}

// round 17
// speedup vs baseline: 1.1232x; 1.0107x over previous
#include <cuda_runtime.h>
#include <cuda_fp16.h>
#include <mma.h>
#include <cstdint>

using namespace nvcuda;

// ---------------- problem constants ----------------
#define Bc 4
#define Lc 4096
#define DMc 2048
#define Hc 32
#define Nc 128
#define Mrows (Bc * Lc)            // 16384
#define MQ (Mrows / 4)             // 4096 (ladder quarter)
#define LDP (2 * Nc + Hc)          // 288
#define SEG 8
#define LSEG (Lc / SEG)            // 512
#define CHk 32
#define CH1 64

// ---------------- scratch (device globals; allocation-free) ----------------
__device__ __half g_xh [(size_t)Mrows * DMc];
__device__ __half g_Wxh[(size_t)DMc * LDP];
__device__ __half g_Wgh[(size_t)DMc * DMc];
__device__ __half g_Woh[(size_t)DMc * DMc];
__device__ float  g_P  [(size_t)Mrows * LDP];
__device__ float  g_Y  [(size_t)Mrows * Hc];
__device__ __half g_gate[(size_t)Mrows * DMc];
__device__ __half g_yf [(size_t)Mrows * DMc];
__device__ float  g_segstate[Bc * Hc * SEG * Nc];
__device__ float  g_segdecay[Bc * Hc * SEG * Nc];
__device__ float  g_seghin  [Bc * Hc * SEG * Nc];

// ---------------- side stream + events (host objects, created once) --------
struct StreamCtx {
    cudaStream_t s1;
    cudaEvent_t e0, eg[4];
    StreamCtx() {
        cudaStreamCreateWithFlags(&s1, cudaStreamNonBlocking);
        cudaEventCreateWithFlags(&e0, cudaEventDisableTiming);
        for (int i = 0; i < 4; i++)
            cudaEventCreateWithFlags(&eg[i], cudaEventDisableTiming);
    }
};
static StreamCtx g_ctx;

// ---------------- cp.async helpers ----------------
__device__ __forceinline__ void cp16(void* smem, const void* gmem, int sz) {
    unsigned s = (unsigned)__cvta_generic_to_shared(smem);
    asm volatile("cp.async.cg.shared.global [%0], [%1], 16, %2;\n"
                 :: "r"(s), "l"(gmem), "r"(sz));
}
__device__ __forceinline__ void cp_commit() {
    asm volatile("cp.async.commit_group;\n");
}
template <int NWAIT>
__device__ __forceinline__ void cp_wait() {
    asm volatile("cp.async.wait_group %0;\n" :: "n"(NWAIT));
}

// ---------------- fused convert: x, Wx, Wg, Wo -> fp16 ----------------
#define C0 (Mrows * DMc / 4)               // x      8388608
#define C1 (C0 + DMc * LDP / 4)            // +Wx     147456
#define C2 (C1 + DMc * DMc / 4)            // +Wg    1048576
#define C3 (C2 + DMc * DMc / 4)            // +Wo    1048576

__device__ __forceinline__ void conv_one(
    int i, const float* __restrict__ x,  const float* __restrict__ Wx,
    const float* __restrict__ Wg, const float* __restrict__ Wo,
    __half* __restrict__ xh,  __half* __restrict__ Wxh,
    __half* __restrict__ Wgh, __half* __restrict__ Woh) {
    const float* src; __half* dst; int off;
    if (i < C0)      { src = x;  dst = xh;  off = i; }
    else if (i < C1) { src = Wx; dst = Wxh; off = i - C0; }
    else if (i < C2) { src = Wg; dst = Wgh; off = i - C1; }
    else             { src = Wo; dst = Woh; off = i - C2; }
    float4 v = reinterpret_cast<const float4*>(src)[off];
    __half2 a = __floats2half2_rn(v.x, v.y);
    __half2 b = __floats2half2_rn(v.z, v.w);
    uint2 r;
    r.x = *reinterpret_cast<uint32_t*>(&a);
    r.y = *reinterpret_cast<uint32_t*>(&b);
    reinterpret_cast<uint2*>(dst)[off] = r;
}

__global__ void __launch_bounds__(512)
conv_all(const float* __restrict__ x,  const float* __restrict__ Wx,
         const float* __restrict__ Wg, const float* __restrict__ Wo,
         __half* __restrict__ xh,  __half* __restrict__ Wxh,
         __half* __restrict__ Wgh, __half* __restrict__ Woh) {
    int base = blockIdx.x * 1024 + threadIdx.x;
    if (base < C3)       conv_one(base,       x, Wx, Wg, Wo, xh, Wxh, Wgh, Woh);
    if (base + 512 < C3) conv_one(base + 512, x, Wx, Wg, Wo, xh, Wxh, Wgh, Woh);
}

// ---------------- wmma GEMM: 128x128 tile, 4 warps, 64x64 warp tile --------
// EPI 0: direct fp32 store (N % 128 == 0)
// EPI 1: staged fp32 store with N edge (P GEMM)
// EPI 2: gate: Ch = half(sigmoid(acc + bias[col])), half2 stores
#define BM 128
#define BN 128
#define BKg 64
#define SKA 72
#define SKB 136
#define A_STG_H (BM * SKA)
#define B_STG_H (BKg * SKB)
#define A_BYTES (3 * A_STG_H * 2)
#define GEMM_DSMEM (A_BYTES + 3 * B_STG_H * 2)   // 107520
#define GT 128                                   // threads per GEMM CTA

template <int EPI>
__global__ void __launch_bounds__(GT)
gemm128(const __half* __restrict__ Ag, const __half* __restrict__ Bg,
        float* __restrict__ Cf, __half* __restrict__ Ch,
        const float* __restrict__ bias, int N, int K) {
    extern __shared__ __align__(16) char dsm[];
    __half* Asm = reinterpret_cast<__half*>(dsm);
    __half* Bsm = reinterpret_cast<__half*>(dsm + A_BYTES);

    const int m0 = blockIdx.y * BM;
    const int n0 = blockIdx.x * BN;
    const int tid = threadIdx.x;
    const int warpId = tid >> 5;          // 0..3
    const int lane = tid & 31;
    const int KT = K / BKg;

    // 4 warps: 2x2 grid of 64x64 warp tiles
    const int row0 = (warpId & 1) * 64;
    const int col0 = (warpId >> 1) * 64;

    wmma::fragment<wmma::accumulator, 16, 16, 16, float> acc[4][4];
#pragma unroll
    for (int i = 0; i < 4; i++)
#pragma unroll
        for (int j = 0; j < 4; j++) wmma::fill_fragment(acc[i][j], 0.f);

    auto load_stage = [&](int slot, int kt) {
        __half* As = Asm + slot * A_STG_H;
        __half* Bs = Bsm + slot * B_STG_H;
        const int k0 = kt * BKg;
#pragma unroll
        for (int j = 0; j < 8; ++j) {            // A: 128x64 = 1024 vec16
            int idx = tid + GT * j;
            int r = idx >> 3, v = idx & 7;
            cp16(As + r * SKA + v * 8,
                 Ag + (size_t)(m0 + r) * K + k0 + v * 8, 16);
        }
#pragma unroll
        for (int j = 0; j < 8; ++j) {            // B: 64x128 = 1024 vec16
            int idx = tid + GT * j;
            int r = idx >> 4, v = idx & 15;
            int col = n0 + v * 8;
            bool ok = (col < N);
            cp16(Bs + r * SKB + v * 8,
                 Bg + (size_t)(k0 + r) * N + (ok ? col : 0), ok ? 16 : 0);
        }
        cp_commit();
    };

    load_stage(0, 0);
    load_stage(1, 1);

    for (int kt = 0; kt < KT; ++kt) {
        cp_wait<1>();
        __syncthreads();
        if (kt + 2 < KT) load_stage((kt + 2) % 3, kt + 2);
        else cp_commit();

        const int slot = kt % 3;
        const __half* Aw = Asm + slot * A_STG_H + row0 * SKA;
        const __half* Bw = Bsm + slot * B_STG_H + col0;

#pragma unroll
        for (int kk = 0; kk < BKg; kk += 16) {
            wmma::fragment<wmma::matrix_a, 16, 16, 16, __half, wmma::row_major> afr[4];
            wmma::fragment<wmma::matrix_b, 16, 16, 16, __half, wmma::row_major> bfr[4];
#pragma unroll
            for (int i = 0; i < 4; i++)
                wmma::load_matrix_sync(afr[i], Aw + (16 * i) * SKA + kk, SKA);
#pragma unroll
            for (int j = 0; j < 4; j++)
                wmma::load_matrix_sync(bfr[j], Bw + kk * SKB + 16 * j, SKB);
#pragma unroll
            for (int i = 0; i < 4; i++)
#pragma unroll
                for (int j = 0; j < 4; j++)
                    wmma::mma_sync(acc[i][j], afr[i], bfr[j], acc[i][j]);
        }
    }
    __syncthreads();

    if (EPI == 0) {
#pragma unroll
        for (int i = 0; i < 4; i++)
#pragma unroll
            for (int j = 0; j < 4; j++)
                wmma::store_matrix_sync(
                    Cf + (size_t)(m0 + row0 + 16 * i) * N + n0 + col0 + 16 * j,
                    acc[i][j], N, wmma::mem_row_major);
        return;
    }

    // staged epilogue via per-warp 16x16 tiles (ld=20)
    float* stage = reinterpret_cast<float*>(dsm) + warpId * (16 * 20);
#pragma unroll
    for (int i = 0; i < 4; i++) {
#pragma unroll
        for (int j = 0; j < 4; j++) {
            wmma::store_matrix_sync(stage, acc[i][j], 20, wmma::mem_row_major);
            __syncwarp();
            if (EPI == 1) {
#pragma unroll
                for (int e = 0; e < 8; ++e) {
                    int idx = lane + 32 * e;
                    int rr = idx >> 4, cc = idx & 15;
                    int row = m0 + row0 + i * 16 + rr;
                    int col = n0 + col0 + j * 16 + cc;
                    if (col < N)
                        Cf[(size_t)row * N + col] = stage[rr * 20 + cc];
                }
            } else {
                // vectorized half2 gate stores
#pragma unroll
                for (int e = 0; e < 4; ++e) {
                    int p = lane + 32 * e;          // 0..127
                    int rr = p >> 3, pc = p & 7;
                    int row = m0 + row0 + i * 16 + rr;
                    int col = n0 + col0 + j * 16 + 2 * pc;
                    float v0 = stage[rr * 20 + 2 * pc]     + __ldg(&bias[col]);
                    float v1 = stage[rr * 20 + 2 * pc + 1] + __ldg(&bias[col + 1]);
                    float g0 = 1.f / (1.f + __expf(-v0));
                    float g1 = 1.f / (1.f + __expf(-v1));
                    *reinterpret_cast<__half2*>(Ch + (size_t)row * N + col) =
                        __floats2half2_rn(g0, g1);
                }
            }
            __syncwarp();
        }
    }
}

// ---------------- segmented scan ----------------
// pass 1 (lean staging): only B columns + own-h db; CH1=64 rows per chunk
__global__ void __launch_bounds__(128)
scan_pass1(const float* __restrict__ P, const float* __restrict__ Amat,
           float* __restrict__ segstate, float* __restrict__ segdecay) {
    __shared__ float sP[CH1][132];           // [.,0..127]=B, [.,128]=db
    const int blk = blockIdx.x;              // ((b*H + h)*SEG + seg)
    const int seg = blk & (SEG - 1);
    const int bh = blk >> 3;
    const int b = bh >> 5, h = bh & 31;
    const int n = threadIdx.x;
    const float Ahn = Amat[h * Nc + n];
    const float* Pb = P + ((size_t)b * Lc + seg * LSEG) * LDP;
    float s = 0.f, sumd = 0.f;

    for (int t0 = 0; t0 < LSEG; t0 += CH1) {
        // stage B cols: CH1 rows x 32 float4
#pragma unroll
        for (int i = threadIdx.x; i < CH1 * 32; i += 128) {
            int row = i >> 5, v = i & 31;
            float4 val = *reinterpret_cast<const float4*>(
                Pb + (size_t)(t0 + row) * LDP + v * 4);
            *reinterpret_cast<float4*>(&sP[row][v * 4]) = val;
        }
        // stage own-h db column
        if (threadIdx.x < CH1)
            sP[threadIdx.x][128] = Pb[(size_t)(t0 + threadIdx.x) * LDP + 2 * Nc + h];
        __syncthreads();
#pragma unroll 4
        for (int i = 0; i < CH1; ++i) {
            float z = sP[i][128] + sP[i][n];
            float d = __logf(1.f + __expf(z));
            float a = __expf(d * Ahn);
            s = fmaf(a, s, d * d);
            sumd += d;
        }
        __syncthreads();
    }
    segstate[blk * Nc + n] = s;
    segdecay[blk * Nc + n] = __expf(Ahn * sumd);
}

__global__ void scan_pass2(const float* __restrict__ state,
                           const float* __restrict__ decay,
                           float* __restrict__ hin) {
    int i = blockIdx.x * blockDim.x + threadIdx.x;
    if (i >= Bc * Hc * Nc) return;
    int bh = i >> 7, n = i & 127;
    float h = 0.f;
#pragma unroll
    for (int s = 0; s < SEG; s++) {
        int idx = (bh * SEG + s) * Nc + n;
        hin[idx] = h;
        h = decay[idx] * h + state[idx];
    }
}

// pass 3 (lean staging): B + C columns + own-h db (260 floats/row)
__global__ void __launch_bounds__(128)
scan_pass3(const float* __restrict__ P, const float* __restrict__ Amat,
           const float* __restrict__ hin, float* __restrict__ Y) {
    __shared__ float sP[CHk][260];           // [.,0..255]=B,C  [.,256]=db
    __shared__ float part[4][CHk];
    const int blk = blockIdx.x;
    const int seg = blk & (SEG - 1);
    const int bh = blk >> 3;
    const int b = bh >> 5, h = bh & 31;
    const int n = threadIdx.x;
    const int warp = n >> 5, lane = n & 31;
    const float Ahn = Amat[h * Nc + n];
    const float* Pb = P + ((size_t)b * Lc + seg * LSEG) * LDP;
    float s = hin[blk * Nc + n];

    for (int t0 = 0; t0 < LSEG; t0 += CHk) {
        // stage B+C cols: CHk rows x 64 float4
#pragma unroll
        for (int i = threadIdx.x; i < CHk * 64; i += 128) {
            int row = i >> 6, v = i & 63;
            float4 val = *reinterpret_cast<const float4*>(
                Pb + (size_t)(t0 + row) * LDP + v * 4);
            *reinterpret_cast<float4*>(&sP[row][v * 4]) = val;
        }
        if (threadIdx.x < CHk)
            sP[threadIdx.x][256] = Pb[(size_t)(t0 + threadIdx.x) * LDP + 2 * Nc + h];
        __syncthreads();
#pragma unroll 4
        for (int i = 0; i < CHk; ++i) {
            float Bn = sP[i][n];
            float Cn = sP[i][Nc + n];
            float z = sP[i][256] + Bn;
            float d = __logf(1.f + __expf(z));
            float a = __expf(d * Ahn);
            s = fmaf(a, s, d * d);
            float v = s * Cn;
            v += __shfl_xor_sync(0xffffffffu, v, 16);
            v += __shfl_xor_sync(0xffffffffu, v, 8);
            v += __shfl_xor_sync(0xffffffffu, v, 4);
            v += __shfl_xor_sync(0xffffffffu, v, 2);
            v += __shfl_xor_sync(0xffffffffu, v, 1);
            if (lane == 0) part[warp][i] = v;
        }
        __syncthreads();
        if (threadIdx.x < CHk) {
            float yv = part[0][threadIdx.x] + part[1][threadIdx.x] +
                       part[2][threadIdx.x] + part[3][threadIdx.x];
            Y[(size_t)(b * Lc + seg * LSEG + t0 + threadIdx.x) * Hc + h] = yv;
        }
        __syncthreads();
    }
}

// ---------------- y_full assembly (operates on a row-range) ----------------
__global__ void yfull_kernel(const __half* __restrict__ xh,
                             const __half* __restrict__ gate,
                             const float* __restrict__ Y,
                             const float* __restrict__ Dp,
                             __half* __restrict__ yf, int n2) {
    int i = blockIdx.x * blockDim.x + threadIdx.x;   // over rows*DM/2 half2
    if (i >= n2) return;
    int m = i >> 10;
    int kk = i & 1023;
    int h = kk >> 5;
    float yv = __ldg(&Y[m * Hc + h]);
    float dp = __ldg(&Dp[h]);
    __half2 xv = reinterpret_cast<const __half2*>(xh)[i];
    __half2 gv = reinterpret_cast<const __half2*>(gate)[i];
    float2 xf = __half22float2(xv);
    float2 gf = __half22float2(gv);
    float r0 = (yv + xf.x * dp) * gf.x;
    float r1 = (yv + xf.y * dp) * gf.y;
    reinterpret_cast<__half2*>(yf)[i] = __floats2half2_rn(r0, r1);
}

// ---------------- launcher ----------------
extern "C" void kernel_launch(void* const* d_in, const int* in_sizes, int n_in,
                              void* d_out, int out_size) {
    const float* x  = (const float*)d_in[0];
    const float* Wx = (const float*)d_in[1];
    const float* Wg = (const float*)d_in[2];
    const float* bg = (const float*)d_in[3];
    const float* Wo = (const float*)d_in[4];
    const float* Am = (const float*)d_in[5];
    const float* Dp = (const float*)d_in[6];
    float* out = (float*)d_out;

    __half *xh, *Wxh, *Wgh, *Woh, *gateh, *yfh;
    float *P, *Y, *sst, *sdc, *shn;
    cudaGetSymbolAddress((void**)&xh,  g_xh);
    cudaGetSymbolAddress((void**)&Wxh, g_Wxh);
    cudaGetSymbolAddress((void**)&Wgh, g_Wgh);
    cudaGetSymbolAddress((void**)&Woh, g_Woh);
    cudaGetSymbolAddress((void**)&P,   g_P);
    cudaGetSymbolAddress((void**)&Y,   g_Y);
    cudaGetSymbolAddress((void**)&gateh, g_gate);
    cudaGetSymbolAddress((void**)&yfh, g_yf);
    cudaGetSymbolAddress((void**)&sst, g_segstate);
    cudaGetSymbolAddress((void**)&sdc, g_segdecay);
    cudaGetSymbolAddress((void**)&shn, g_seghin);

    cudaFuncSetAttribute(gemm128<0>, cudaFuncAttributeMaxDynamicSharedMemorySize, GEMM_DSMEM);
    cudaFuncSetAttribute(gemm128<1>, cudaFuncAttributeMaxDynamicSharedMemorySize, GEMM_DSMEM);
    cudaFuncSetAttribute(gemm128<2>, cudaFuncAttributeMaxDynamicSharedMemorySize, GEMM_DSMEM);

    const int T = 256;
    const size_t QOFF = (size_t)MQ * DMc;     // element offset of one quarter

    // --- main stream (s0): conv -> P -> scan chain ---
    conv_all<<<(C3 + 1023) / 1024, 512>>>(x, Wx, Wg, Wo, xh, Wxh, Wgh, Woh);
    cudaEventRecord(g_ctx.e0, 0);

    gemm128<1><<<dim3((LDP + BN - 1) / BN, Mrows / BM), GT, GEMM_DSMEM>>>(
        xh, Wxh, P, nullptr, nullptr, LDP, DMc);

    scan_pass1<<<Bc * Hc * SEG, 128>>>(P, Am, sst, sdc);
    scan_pass2<<<(Bc * Hc * Nc + T - 1) / T, T>>>(sst, sdc, shn);
    scan_pass3<<<Bc * Hc * SEG, 128>>>(P, Am, shn, Y);

    // --- side stream (s1): gate GEMM in 4 M-quarters ---
    cudaStreamWaitEvent(g_ctx.s1, g_ctx.e0, 0);
    for (int q = 0; q < 4; ++q) {
        gemm128<2><<<dim3(DMc / BN, MQ / BM), GT, GEMM_DSMEM, g_ctx.s1>>>(
            xh + q * QOFF, Wgh, nullptr, gateh + q * QOFF, bg, DMc, DMc);
        cudaEventRecord(g_ctx.eg[q], g_ctx.s1);
    }

    // --- main stream: consume quarters as they land (scan already ordered) ---
    const int n2q = MQ * (DMc / 2);
    for (int q = 0; q < 4; ++q) {
        cudaStreamWaitEvent(0, g_ctx.eg[q], 0);
        yfull_kernel<<<(n2q + T - 1) / T, T>>>(
            xh + q * QOFF, gateh + q * QOFF, Y + (size_t)q * MQ * Hc, Dp,
            yfh + q * QOFF, n2q);
        gemm128<0><<<dim3(DMc / BN, MQ / BM), GT, GEMM_DSMEM>>>(
            yfh + q * QOFF, Woh, out + q * QOFF, nullptr, nullptr, DMc, DMc);
    }
}